// round 2
// baseline (speedup 1.0000x reference)
#include <cuda_runtime.h>

// Problem constants
#define NQ   50000
#define MS   50000
#define HN   32
#define KKP  15
#define CINV 64
#define COUTV 128
#define KDIM (KKP * CINV)   // 960

// Scratch: wf[n][k][cin] fp32 (192 MB) — static device global (no allocations).
__device__ float g_wf[(size_t)NQ * KKP * CINV];

// ---------------------------------------------------------------------------
// Kernel 1: per-query gather + kernel-point influence weights + H-reduction.
// One block (128 threads) per query point n.
//   w[h][k]   = relu(1 - |s[idx[h]] - q[n] - kp[k]| / 0.072)
//   wf[k][c]  = sum_h w[h][k] * x[idx[h]][c]
// ---------------------------------------------------------------------------
__global__ __launch_bounds__(128) void kpconv_gather(
    const float* __restrict__ q,
    const float* __restrict__ s,
    const int* __restrict__ nb,          // int32 (JAX x64-disabled downcast)
    const float* __restrict__ x,
    const float* __restrict__ kp)
{
    const int n = blockIdx.x;
    const int t = threadIdx.x;

    __shared__ float xs[HN * CINV];     // 8 KB: neighbor feature rows
    __shared__ float wk[HN][KKP];       // influence weights
    __shared__ float nbp[HN][3];        // neighbor coords (centered)
    __shared__ int   idx[HN];
    __shared__ float kps[KKP * 3];

    if (t < HN) {
        int j = nb[(size_t)n * HN + t];
        // safety clamp: no-op for valid data, avoids IMA on dtype surprises
        j = j < 0 ? 0 : (j >= MS ? MS - 1 : j);
        idx[t] = j;
    }
    if (t < KKP * 3) kps[t] = kp[t];
    __syncthreads();

    // centered neighbor coordinates
    const float qx = q[n * 3 + 0];
    const float qy = q[n * 3 + 1];
    const float qz = q[n * 3 + 2];
    if (t < HN) {
        const int j = idx[t];
        nbp[t][0] = s[j * 3 + 0] - qx;
        nbp[t][1] = s[j * 3 + 1] - qy;
        nbp[t][2] = s[j * 3 + 2] - qz;
    }

    // stage neighbor x rows into smem: 4 threads per row, 64B (4 float4) each
    {
        const int h  = t >> 2;          // 0..31
        const int c4 = (t & 3) * 4;     // float4 index within row (16 per row)
        const int j  = idx[h];
        const float4* src = reinterpret_cast<const float4*>(x) + (size_t)j * (CINV / 4);
        float4* dst = reinterpret_cast<float4*>(xs) + h * (CINV / 4);
#pragma unroll
        for (int u = 0; u < 4; u++) dst[c4 + u] = src[c4 + u];
    }
    __syncthreads();

    // influence weights: 480 (h,k) pairs
    for (int i = t; i < HN * KKP; i += 128) {
        const int h = i / KKP;
        const int k = i - h * KKP;
        const float dx = nbp[h][0] - kps[k * 3 + 0];
        const float dy = nbp[h][1] - kps[k * 3 + 1];
        const float dz = nbp[h][2] - kps[k * 3 + 2];
        const float d2 = dx * dx + dy * dy + dz * dz;
        const float w  = 1.0f - sqrtf(d2) * (1.0f / 0.072f);
        wk[h][k] = w > 0.0f ? w : 0.0f;
    }
    __syncthreads();

    // H-reduction: thread owns (k0, k0+8) x one float4 column group
    const int c4 = t & 15;      // float4 column index (c = 4*c4)
    const int kg = t >> 4;      // 0..7
    const int k0 = kg;
    const int k1 = kg + 8;
    const bool has1 = (k1 < KKP);

    float4 a0 = make_float4(0.f, 0.f, 0.f, 0.f);
    float4 a1 = make_float4(0.f, 0.f, 0.f, 0.f);
    const float4* xs4 = reinterpret_cast<const float4*>(xs);
#pragma unroll
    for (int h = 0; h < HN; h++) {
        const float4 xv = xs4[h * (CINV / 4) + c4];
        const float w0 = wk[h][k0];
        a0.x += w0 * xv.x; a0.y += w0 * xv.y; a0.z += w0 * xv.z; a0.w += w0 * xv.w;
        if (has1) {
            const float w1 = wk[h][k1];
            a1.x += w1 * xv.x; a1.y += w1 * xv.y; a1.z += w1 * xv.z; a1.w += w1 * xv.w;
        }
    }

    float4* wf4 = reinterpret_cast<float4*>(g_wf);
    wf4[((size_t)n * KKP + k0) * (CINV / 4) + c4] = a0;
    if (has1)
        wf4[((size_t)n * KKP + k1) * (CINV / 4) + c4] = a1;
}

// ---------------------------------------------------------------------------
// Kernel 2: SGEMM  out[N,128] = wf[N,960] @ W[960,128] + bias
// 128x128 block tile, BK=16, 256 threads, 8x8 microtile per thread.
// ---------------------------------------------------------------------------
__global__ __launch_bounds__(256) void kpconv_gemm(
    const float* __restrict__ B,     // weights [960][128]
    const float* __restrict__ bias,  // [128]
    float* __restrict__ Cout)        // [N][128]
{
    __shared__ float As[16][132];    // A-tile transposed [k][m], padded
    __shared__ float Bs[16][128];    // B-tile [k][n]

    const int t  = threadIdx.x;
    const int bm = blockIdx.x * 128;
    const int tx = t & 15;           // 16 column groups
    const int ty = t >> 4;           // 16 row groups

    float acc[8][8];
#pragma unroll
    for (int i = 0; i < 8; i++)
#pragma unroll
        for (int j = 0; j < 8; j++) acc[i][j] = 0.0f;

    const float* A = g_wf;

    for (int kt = 0; kt < KDIM; kt += 16) {
        // Load A tile (128 x 16), transposed into As[k][m]
#pragma unroll
        for (int r = 0; r < 2; r++) {
            const int id = t + r * 256;
            const int m  = id >> 2;            // 0..127
            const int kc = id & 3;             // 0..3 (4 k's each)
            const int gm = bm + m;
            float4 v = make_float4(0.f, 0.f, 0.f, 0.f);
            if (gm < NQ)
                v = *reinterpret_cast<const float4*>(A + (size_t)gm * KDIM + kt + kc * 4);
            As[kc * 4 + 0][m] = v.x;
            As[kc * 4 + 1][m] = v.y;
            As[kc * 4 + 2][m] = v.z;
            As[kc * 4 + 3][m] = v.w;
        }
        // Load B tile (16 x 128)
#pragma unroll
        for (int r = 0; r < 2; r++) {
            const int id = t + r * 256;
            const int k  = id >> 5;            // 0..15
            const int n4 = id & 31;            // 0..31
            const float4 v = *reinterpret_cast<const float4*>(
                B + (size_t)(kt + k) * COUTV + n4 * 4);
            *reinterpret_cast<float4*>(&Bs[k][n4 * 4]) = v;
        }
        __syncthreads();

#pragma unroll
        for (int kk = 0; kk < 16; kk++) {
            float a[8], b[8];
            const float4 av0 = *reinterpret_cast<const float4*>(&As[kk][ty * 8 + 0]);
            const float4 av1 = *reinterpret_cast<const float4*>(&As[kk][ty * 8 + 4]);
            const float4 bv0 = *reinterpret_cast<const float4*>(&Bs[kk][tx * 8 + 0]);
            const float4 bv1 = *reinterpret_cast<const float4*>(&Bs[kk][tx * 8 + 4]);
            a[0]=av0.x; a[1]=av0.y; a[2]=av0.z; a[3]=av0.w;
            a[4]=av1.x; a[5]=av1.y; a[6]=av1.z; a[7]=av1.w;
            b[0]=bv0.x; b[1]=bv0.y; b[2]=bv0.z; b[3]=bv0.w;
            b[4]=bv1.x; b[5]=bv1.y; b[6]=bv1.z; b[7]=bv1.w;
#pragma unroll
            for (int i = 0; i < 8; i++)
#pragma unroll
                for (int j = 0; j < 8; j++)
                    acc[i][j] += a[i] * b[j];
        }
        __syncthreads();
    }

    // Epilogue: + bias, write out
    float bb[8];
#pragma unroll
    for (int j = 0; j < 8; j++) bb[j] = bias[tx * 8 + j];

#pragma unroll
    for (int i = 0; i < 8; i++) {
        const int gm = bm + ty * 8 + i;
        if (gm < NQ) {
            float4 o0, o1;
            o0.x = acc[i][0] + bb[0]; o0.y = acc[i][1] + bb[1];
            o0.z = acc[i][2] + bb[2]; o0.w = acc[i][3] + bb[3];
            o1.x = acc[i][4] + bb[4]; o1.y = acc[i][5] + bb[5];
            o1.z = acc[i][6] + bb[6]; o1.w = acc[i][7] + bb[7];
            float4* dst = reinterpret_cast<float4*>(Cout + (size_t)gm * COUTV + tx * 8);
            dst[0] = o0;
            dst[1] = o1;
        }
    }
}

// ---------------------------------------------------------------------------
extern "C" void kernel_launch(void* const* d_in, const int* in_sizes, int n_in,
                              void* d_out, int out_size)
{
    const float* q    = (const float*)d_in[0];      // [N,3]
    const float* s    = (const float*)d_in[1];      // [M,3]
    const int*   nb   = (const int*)d_in[2];        // [N,H] int32
    const float* x    = (const float*)d_in[3];      // [M,64]
    const float* kp   = (const float*)d_in[4];      // [15,3]
    const float* w    = (const float*)d_in[5];      // [15,64,128]
    const float* bias = (const float*)d_in[6];      // [128]
    float*       out  = (float*)d_out;              // [N,128]

    kpconv_gather<<<NQ, 128>>>(q, s, nb, x, kp);
    kpconv_gemm<<<(NQ + 127) / 128, 256>>>(w, bias, out);
}

// round 4
// speedup vs baseline: 2.3013x; 2.3013x over previous
#include <cuda_runtime.h>
#include <cuda_bf16.h>
#include <cstdint>

// Problem constants
#define NQ    50000
#define MS    50000
#define HN    32
#define KKP   15
#define KP16  16
#define CINV  64
#define COUTV 128
#define KD    1024          // scratch row length (16 kp x 64 cin), kd>=960 is zero padding
#define KREAL 960
#define NPAD  50048         // 391 * 128
#define BK    32
#define NITER 30            // 960 / 32

// ---------------------------------------------------------------------------
// Scratch (device globals; zero-initialized at load -> padding stays zero)
// ---------------------------------------------------------------------------
__device__ __nv_bfloat16 g_wfh[(size_t)NPAD * KD];   // wf hi  [n][kd]
__device__ __nv_bfloat16 g_wfl[(size_t)NPAD * KD];   // wf lo
__device__ __nv_bfloat16 g_wth[(size_t)COUTV * KD];  // W^T hi [cout][kd]
__device__ __nv_bfloat16 g_wtl[(size_t)COUTV * KD];  // W^T lo

// ---------------------------------------------------------------------------
// mma / ldmatrix / cp.async helpers (baseline PTX features, no 'a' target)
// ---------------------------------------------------------------------------
__device__ __forceinline__ void ldsm4(uint32_t* r, uint32_t a) {
    asm volatile("ldmatrix.sync.aligned.m8n8.x4.shared.b16 {%0,%1,%2,%3}, [%4];"
                 : "=r"(r[0]), "=r"(r[1]), "=r"(r[2]), "=r"(r[3]) : "r"(a));
}
__device__ __forceinline__ void ldsm2(uint32_t* r, uint32_t a) {
    asm volatile("ldmatrix.sync.aligned.m8n8.x2.shared.b16 {%0,%1}, [%2];"
                 : "=r"(r[0]), "=r"(r[1]) : "r"(a));
}
__device__ __forceinline__ void mma16816(float* c, const uint32_t* a, const uint32_t* b) {
    asm volatile(
        "mma.sync.aligned.m16n8k16.row.col.f32.bf16.bf16.f32 "
        "{%0,%1,%2,%3}, {%4,%5,%6,%7}, {%8,%9}, {%0,%1,%2,%3};"
        : "+f"(c[0]), "+f"(c[1]), "+f"(c[2]), "+f"(c[3])
        : "r"(a[0]), "r"(a[1]), "r"(a[2]), "r"(a[3]), "r"(b[0]), "r"(b[1]));
}
__device__ __forceinline__ void cp16(uint32_t saddr, const void* gaddr) {
    asm volatile("cp.async.cg.shared.global [%0], [%1], 16;"
                 :: "r"(saddr), "l"(gaddr) : "memory");
}

// ---------------------------------------------------------------------------
// Kernel 0: weights -> W^T, bf16 hi/lo split.  Wt[cout][kd] = W[kd][cout]
// ---------------------------------------------------------------------------
__global__ __launch_bounds__(256) void kp_prep(const float* __restrict__ W) {
    const int id = blockIdx.x * 256 + threadIdx.x;       // 0 .. 131071
    const int kd = id & (KD - 1);
    const int n  = id >> 10;
    float v = (kd < KREAL) ? W[kd * COUTV + n] : 0.0f;
    __nv_bfloat16 h = __float2bfloat16_rn(v);
    __nv_bfloat16 l = __float2bfloat16_rn(v - __bfloat162float(h));
    g_wth[id] = h;
    g_wtl[id] = l;
}

// ---------------------------------------------------------------------------
// Kernel 1: gather + influence weights + H-reduction -> bf16 hi/lo scratch.
// Block = 128 threads = 8 queries x 16 c4-groups. Thread owns 16 k-accumulators.
// ---------------------------------------------------------------------------
__global__ __launch_bounds__(128) void kpconv_gather(
    const float* __restrict__ q,
    const float* __restrict__ s,
    const int* __restrict__ nb,
    const float* __restrict__ x,
    const float* __restrict__ kp)
{
    __shared__ int   idxs[8][HN];
    __shared__ float wk[8][HN][KP16];
    __shared__ float kps[48];

    const int t  = threadIdx.x;
    const int n0 = blockIdx.x * 8;
    const int tq = t >> 4;
    const int tc = t & 15;
    const int n  = n0 + tq;

    if (t < KKP * 3) kps[t] = kp[t];
#pragma unroll
    for (int i = t; i < 8 * HN; i += 128) {
        const int qq = i >> 5, h = i & 31;
        int j = nb[(size_t)(n0 + qq) * HN + h];
        j = j < 0 ? 0 : (j >= MS ? MS - 1 : j);
        idxs[qq][h] = j;
    }
    __syncthreads();

    // influence weights: thread covers h = tc and tc+16 for its query
    {
        const float qx = q[n * 3 + 0];
        const float qy = q[n * 3 + 1];
        const float qz = q[n * 3 + 2];
#pragma unroll
        for (int hh = 0; hh < 2; hh++) {
            const int h = tc + hh * 16;
            const int j = idxs[tq][h];
            const float nx = s[j * 3 + 0] - qx;
            const float ny = s[j * 3 + 1] - qy;
            const float nz = s[j * 3 + 2] - qz;
#pragma unroll
            for (int k = 0; k < KKP; k++) {
                const float dx = nx - kps[k * 3 + 0];
                const float dy = ny - kps[k * 3 + 1];
                const float dz = nz - kps[k * 3 + 2];
                const float d2 = dx * dx + dy * dy + dz * dz;
                const float w  = 1.0f - sqrtf(d2) * (1.0f / 0.072f);
                wk[tq][h][k] = w > 0.0f ? w : 0.0f;
            }
            wk[tq][h][15] = 0.0f;
        }
    }
    __syncthreads();

    // H-reduction: acc[k] (float4 over cin group) for all k
    float4 acc[KP16];
#pragma unroll
    for (int k = 0; k < KP16; k++) acc[k] = make_float4(0.f, 0.f, 0.f, 0.f);

    const float4* x4 = reinterpret_cast<const float4*>(x);
#pragma unroll 4
    for (int h = 0; h < HN; h++) {
        const int j = idxs[tq][h];
        const float4 xv = x4[(size_t)j * (CINV / 4) + tc];
        const float4* wrow = reinterpret_cast<const float4*>(&wk[tq][h][0]);
        float wv[KP16];
#pragma unroll
        for (int g = 0; g < 4; g++) {
            const float4 wq = wrow[g];
            wv[g * 4 + 0] = wq.x; wv[g * 4 + 1] = wq.y;
            wv[g * 4 + 2] = wq.z; wv[g * 4 + 3] = wq.w;
        }
#pragma unroll
        for (int k = 0; k < KP16; k++) {
            const float w = wv[k];
            acc[k].x += w * xv.x; acc[k].y += w * xv.y;
            acc[k].z += w * xv.z; acc[k].w += w * xv.w;
        }
    }

    // store bf16 hi/lo (uint2 = 4 bf16 each); skip k=15 (stays zero)
    uint2* outh = reinterpret_cast<uint2*>(g_wfh);
    uint2* outl = reinterpret_cast<uint2*>(g_wfl);
#pragma unroll
    for (int k = 0; k < KKP; k++) {
        float a[4] = {acc[k].x, acc[k].y, acc[k].z, acc[k].w};
        __nv_bfloat16 hb[4], lb[4];
#pragma unroll
        for (int u = 0; u < 4; u++) {
            hb[u] = __float2bfloat16_rn(a[u]);
            lb[u] = __float2bfloat16_rn(a[u] - __bfloat162float(hb[u]));
        }
        __nv_bfloat162 h01, h23, l01, l23;
        h01.x = hb[0]; h01.y = hb[1]; h23.x = hb[2]; h23.y = hb[3];
        l01.x = lb[0]; l01.y = lb[1]; l23.x = lb[2]; l23.y = lb[3];
        const size_t o = (size_t)n * (KD / 4) + k * 16 + tc;
        outh[o] = make_uint2(*reinterpret_cast<uint32_t*>(&h01),
                             *reinterpret_cast<uint32_t*>(&h23));
        outl[o] = make_uint2(*reinterpret_cast<uint32_t*>(&l01),
                             *reinterpret_cast<uint32_t*>(&l23));
    }
}

// ---------------------------------------------------------------------------
// Kernel 2: bf16 mma.sync GEMM  out[N,128] = wf[N,960] @ W[960,128] + bias
// Block tile 128x128, 8 warps (64x32 warp tiles), BK=32, cp.async double buffer.
// 3-product bf16 hi/lo split for fp32-grade accuracy.
// ---------------------------------------------------------------------------
#define ROWB  80                 // smem bytes per 32-bf16 row (64B + 16B pad)
#define TILEB (128 * ROWB)       // 10240
#define BUFB  (4 * TILEB)        // Ah, Al, Bh, Bl
#define SMEM_GEMM (2 * BUFB + 512)

__global__ __launch_bounds__(256) void kpconv_gemm_mma(
    const float* __restrict__ bias, float* __restrict__ out)
{
    extern __shared__ char sm[];
    const int t    = threadIdx.x;
    const int lane = t & 31;
    const int wid  = t >> 5;
    const int wm   = (wid >> 2) * 64;   // 0 or 64
    const int wn   = (wid & 3) * 32;    // 0,32,64,96
    const int bm   = blockIdx.x * 128;

    float* sbias = reinterpret_cast<float*>(sm + 2 * BUFB);
    if (t < COUTV) sbias[t] = bias[t];

    const uint32_t smb = (uint32_t)__cvta_generic_to_shared(sm);

    const uint4* gAh = reinterpret_cast<const uint4*>(g_wfh);
    const uint4* gAl = reinterpret_cast<const uint4*>(g_wfl);
    const uint4* gBh = reinterpret_cast<const uint4*>(g_wth);
    const uint4* gBl = reinterpret_cast<const uint4*>(g_wtl);

    // per-thread load slots: id in [0,512), row=id>>2, seg=id&3 (16B each)
    const int r0 = t >> 2, s0 = t & 3;
    const int r1 = (t + 256) >> 2, s1 = t & 3;   // second slot, rows 64..127

    float acc[4][4][4];
#pragma unroll
    for (int mi = 0; mi < 4; mi++)
#pragma unroll
        for (int ni = 0; ni < 4; ni++)
#pragma unroll
            for (int e = 0; e < 4; e++) acc[mi][ni][e] = 0.0f;

    // ldmatrix per-lane address components
    const int a_r = lane & 15, a_c = lane >> 4;         // A: row, k-half
    const int b_r = lane & 7,  b_c = (lane >> 3) & 1;   // B: row(n), k-half

    auto prefetch = [&](int it, int buf) {
        const uint32_t base = smb + buf * BUFB;
#pragma unroll
        for (int j = 0; j < 2; j++) {
            const int row = j ? r1 : r0;
            const int seg = j ? s1 : s0;
            const uint32_t d = base + row * ROWB + seg * 16;
            const size_t ga = (size_t)(bm + row) * (KD / 8) + it * 4 + seg;
            const size_t gb = (size_t)row * (KD / 8) + it * 4 + seg;
            cp16(d + 0 * TILEB, gAh + ga);
            cp16(d + 1 * TILEB, gAl + ga);
            cp16(d + 2 * TILEB, gBh + gb);
            cp16(d + 3 * TILEB, gBl + gb);
        }
        asm volatile("cp.async.commit_group;" ::: "memory");
    };

    prefetch(0, 0);

    for (int it = 0; it < NITER; it++) {
        const int buf = it & 1;
        if (it + 1 < NITER) {
            prefetch(it + 1, buf ^ 1);
            asm volatile("cp.async.wait_group 1;" ::: "memory");
        } else {
            asm volatile("cp.async.wait_group 0;" ::: "memory");
        }
        __syncthreads();

        const uint32_t base = smb + buf * BUFB;
#pragma unroll
        for (int ks = 0; ks < 2; ks++) {
            uint32_t ah[4][4], al[4][4], bh[4][2], bl[4][2];
#pragma unroll
            for (int mi = 0; mi < 4; mi++) {
                const uint32_t ao = base + (wm + mi * 16 + a_r) * ROWB + ks * 32 + a_c * 16;
                ldsm4(ah[mi], ao);
                ldsm4(al[mi], ao + TILEB);
            }
#pragma unroll
            for (int ni = 0; ni < 4; ni++) {
                const uint32_t bo = base + 2 * TILEB +
                                    (wn + ni * 8 + b_r) * ROWB + ks * 32 + b_c * 16;
                ldsm2(bh[ni], bo);
                ldsm2(bl[ni], bo + TILEB);
            }
#pragma unroll
            for (int mi = 0; mi < 4; mi++)
#pragma unroll
                for (int ni = 0; ni < 4; ni++) {
                    mma16816(acc[mi][ni], ah[mi], bh[ni]);
                    mma16816(acc[mi][ni], ah[mi], bl[ni]);
                    mma16816(acc[mi][ni], al[mi], bh[ni]);
                }
        }
        __syncthreads();
    }

    // epilogue: c frag (m = t/4 + {0,8}, n = (t%4)*2 + {0,1}) + bias
    const int er = lane >> 2;
    const int ec = (lane & 3) * 2;
#pragma unroll
    for (int mi = 0; mi < 4; mi++) {
#pragma unroll
        for (int half = 0; half < 2; half++) {
            const int gm = bm + wm + mi * 16 + er + half * 8;
            if (gm < NQ) {
#pragma unroll
                for (int ni = 0; ni < 4; ni++) {
                    const int n = wn + ni * 8 + ec;
                    float2 v;
                    v.x = acc[mi][ni][half * 2 + 0] + sbias[n + 0];
                    v.y = acc[mi][ni][half * 2 + 1] + sbias[n + 1];
                    *reinterpret_cast<float2*>(out + (size_t)gm * COUTV + n) = v;
                }
            }
        }
    }
}

// ---------------------------------------------------------------------------
extern "C" void kernel_launch(void* const* d_in, const int* in_sizes, int n_in,
                              void* d_out, int out_size)
{
    const float* q    = (const float*)d_in[0];      // [N,3]
    const float* s    = (const float*)d_in[1];      // [M,3]
    const int*   nb   = (const int*)d_in[2];        // [N,H] int32
    const float* x    = (const float*)d_in[3];      // [M,64]
    const float* kp   = (const float*)d_in[4];      // [15,3]
    const float* w    = (const float*)d_in[5];      // [15,64,128]
    const float* bias = (const float*)d_in[6];      // [128]
    float*       out  = (float*)d_out;              // [N,128]

    cudaFuncSetAttribute(kpconv_gemm_mma,
                         cudaFuncAttributeMaxDynamicSharedMemorySize, SMEM_GEMM);

    kp_prep<<<512, 256>>>(w);
    kpconv_gather<<<NQ / 8, 128>>>(q, s, nb, x, kp);
    kpconv_gemm_mma<<<NPAD / 128, 256, SMEM_GEMM>>>(bias, out);
}